// round 1
// baseline (speedup 1.0000x reference)
#include <cuda_runtime.h>

#define N_CLASSES 256
#define DIM 128
#define KC 32              // DIM / 4 (float4 chunks per row)

// Scratch (allocation-free rule: __device__ globals)
__device__ float g_psum[N_CLASSES * DIM];
__device__ float g_pcount[N_CLASSES];
__device__ float g_proto[N_CLASSES * DIM];
__device__ float g_pnorm[N_CLASSES];

// ---------------------------------------------------------------------------
// k0: zero the accumulators
// ---------------------------------------------------------------------------
__global__ void zero_kernel() {
    int i = blockIdx.x * blockDim.x + threadIdx.x;
    if (i < N_CLASSES * DIM) g_psum[i] = 0.0f;
    if (i < N_CLASSES)       g_pcount[i] = 0.0f;
}

// ---------------------------------------------------------------------------
// k1: segment-sum via global f32 atomics (REDG). One thread per float4 of
// support. Spread over 32768 addresses -> low contention.
// ---------------------------------------------------------------------------
__global__ void accum_kernel(const float* __restrict__ support,
                             const int* __restrict__ labels, int S) {
    int idx = blockIdx.x * blockDim.x + threadIdx.x;
    if (idx >= S * KC) return;
    int r  = idx >> 5;       // support row
    int c4 = idx & 31;       // float4 chunk within row
    int lbl = labels[r];
    float4 v = ((const float4*)support)[idx];
    float* dst = &g_psum[lbl * DIM + c4 * 4];
    atomicAdd(dst + 0, v.x);
    atomicAdd(dst + 1, v.y);
    atomicAdd(dst + 2, v.z);
    atomicAdd(dst + 3, v.w);
    if (c4 == 0) atomicAdd(&g_pcount[lbl], 1.0f);
}

// ---------------------------------------------------------------------------
// k2: prototypes = sums / max(count,1); also pnorm[c] = ||proto_c||^2
// One block (128 threads) per class.
// ---------------------------------------------------------------------------
__global__ void finalize_kernel() {
    int c = blockIdx.x;
    int d = threadIdx.x;
    float cnt = fmaxf(g_pcount[c], 1.0f);
    float v = g_psum[c * DIM + d] / cnt;
    g_proto[c * DIM + d] = v;
    float s = v * v;
    #pragma unroll
    for (int o = 16; o > 0; o >>= 1) s += __shfl_xor_sync(0xffffffffu, s, o);
    __shared__ float ws[4];
    if ((d & 31) == 0) ws[d >> 5] = s;
    __syncthreads();
    if (d == 0) g_pnorm[c] = ws[0] + ws[1] + ws[2] + ws[3];
}

// ---------------------------------------------------------------------------
// k3: main GEMM-like kernel.
// out[m][n] = 2 * dot(x_m, proto_n) - ||x_m||^2 - ||proto_n||^2
//
// BM=BN=64, K=128 fully resident in smem. 256 threads (16x16), TM=TN=4.
// Packed fma.rn.f32x2 along K: a float4 fragment = two 64-bit f32x2 pairs,
// so 2 FMAs/instruction with zero repacking.
// Smem stored as float4 rows with XOR swizzle kc' = kc ^ ((row>>2)&7):
//   - STS conflict-free (each phase hits distinct bank-quads)
//   - b-frag LDS 2-way max, a-frag broadcast.
// ---------------------------------------------------------------------------
#define BM 64
#define BN 64
#define GEMM_SMEM (2 * BM * DIM * 4 + BM * 4)   // 65792 bytes

__device__ __forceinline__ void fma2(unsigned long long& acc,
                                     unsigned long long a,
                                     unsigned long long b) {
    asm("fma.rn.f32x2 %0, %1, %2, %0;" : "+l"(acc) : "l"(a), "l"(b));
}

__global__ void __launch_bounds__(256, 2)
gemm_kernel(const float* __restrict__ x, float* __restrict__ out) {
    extern __shared__ float4 sm4[];
    float4* As = sm4;               // [64][32] float4, swizzled
    float4* Bs = sm4 + BM * KC;     // [64][32] float4, swizzled
    float*  xnorm_s = (float*)(sm4 + 2 * BM * KC);  // [64]

    int tid = threadIdx.x;
    int tx = tid & 15;              // n direction
    int ty = tid >> 4;              // m direction
    int m0 = blockIdx.x * BM;
    int n0 = blockIdx.y * BN;

    const float4* x4 = ((const float4*)x)       + (size_t)m0 * KC;
    const float4* p4 = ((const float4*)g_proto) + (size_t)n0 * KC;

    // Load both tiles (2048 float4 each), coalesced gmem, swizzled smem store.
    #pragma unroll
    for (int i = 0; i < 8; i++) {
        int t  = tid + i * 256;
        int r  = t >> 5;
        int kc = t & 31;
        int swz = kc ^ ((r >> 2) & 7);
        As[r * KC + swz] = x4[r * KC + kc];
        Bs[r * KC + swz] = p4[r * KC + kc];
    }
    __syncthreads();

    // Per-row ||x||^2 from the smem tile (order-independent sum, swizzle ok)
    if (tid < BM) {
        float s = 0.0f;
        #pragma unroll
        for (int kc = 0; kc < KC; kc++) {
            float4 v = As[tid * KC + kc];
            s += v.x * v.x + v.y * v.y + v.z * v.z + v.w * v.w;
        }
        xnorm_s[tid] = s;
    }
    __syncthreads();

    unsigned long long acc[4][4] = {};   // f32x2 {0,0} == 0ull
    const int sa = ty & 7;               // swizzle const for rows 4ty..4ty+3
    const int sb = tx & 7;
    const float4* Arow = As + (4 * ty) * KC;
    const float4* Brow = Bs + (4 * tx) * KC;

    #pragma unroll
    for (int kc = 0; kc < KC; kc++) {
        ulonglong2 a[4], b[4];
        int ka = kc ^ sa;
        int kb = kc ^ sb;
        #pragma unroll
        for (int i = 0; i < 4; i++) {
            a[i] = *(const ulonglong2*)(Arow + i * KC + ka);
            b[i] = *(const ulonglong2*)(Brow + i * KC + kb);
        }
        #pragma unroll
        for (int i = 0; i < 4; i++) {
            #pragma unroll
            for (int j = 0; j < 4; j++) {
                fma2(acc[i][j], a[i].x, b[j].x);
                fma2(acc[i][j], a[i].y, b[j].y);
            }
        }
    }

    // Epilogue: out = 2*dot - xnorm - pnorm  (== -dist)
    float pn[4];
    #pragma unroll
    for (int j = 0; j < 4; j++) pn[j] = g_pnorm[n0 + 4 * tx + j];

    #pragma unroll
    for (int i = 0; i < 4; i++) {
        int m = m0 + 4 * ty + i;
        float xn = xnorm_s[4 * ty + i];
        float r0, r1, r2, r3;
        {
            unsigned long long v = acc[i][0];
            r0 = 2.0f * (__uint_as_float((unsigned)v) +
                         __uint_as_float((unsigned)(v >> 32))) - xn - pn[0];
        }
        {
            unsigned long long v = acc[i][1];
            r1 = 2.0f * (__uint_as_float((unsigned)v) +
                         __uint_as_float((unsigned)(v >> 32))) - xn - pn[1];
        }
        {
            unsigned long long v = acc[i][2];
            r2 = 2.0f * (__uint_as_float((unsigned)v) +
                         __uint_as_float((unsigned)(v >> 32))) - xn - pn[2];
        }
        {
            unsigned long long v = acc[i][3];
            r3 = 2.0f * (__uint_as_float((unsigned)v) +
                         __uint_as_float((unsigned)(v >> 32))) - xn - pn[3];
        }
        *(float4*)&out[(size_t)m * N_CLASSES + n0 + 4 * tx] =
            make_float4(r0, r1, r2, r3);
    }
}

// ---------------------------------------------------------------------------
extern "C" void kernel_launch(void* const* d_in, const int* in_sizes, int n_in,
                              void* d_out, int out_size) {
    const float* x       = (const float*)d_in[0];
    const float* support = (const float*)d_in[1];
    const int*   labels  = (const int*)d_in[2];
    float* out = (float*)d_out;

    int M = in_sizes[0] / DIM;   // 8192
    int S = in_sizes[2];         // 4096

    zero_kernel<<<(N_CLASSES * DIM + 255) / 256, 256>>>();
    accum_kernel<<<(S * KC + 255) / 256, 256>>>(support, labels, S);
    finalize_kernel<<<N_CLASSES, DIM>>>();

    cudaFuncSetAttribute(gemm_kernel,
                         cudaFuncAttributeMaxDynamicSharedMemorySize, GEMM_SMEM);
    gemm_kernel<<<dim3(M / BM, N_CLASSES / BN), 256, GEMM_SMEM>>>(x, out);
}

// round 2
// speedup vs baseline: 1.6250x; 1.6250x over previous
#include <cuda_runtime.h>
#include <cuda_fp16.h>

#define M_ROWS 8192
#define N_CLASSES 256
#define DIM 128

// ---------------- scratch (__device__ globals; allocation-free rule) -------
__device__ float g_psum[N_CLASSES * DIM];
__device__ float g_pcount[N_CLASSES];
__device__ float g_pnorm[N_CLASSES];
__device__ float g_xnorm[M_ROWS];
__device__ __align__(16) __half g_hp[N_CLASSES * DIM];
__device__ __align__(16) __half g_rp[N_CLASSES * DIM];
__device__ __align__(16) __half g_hx[M_ROWS * DIM];
__device__ __align__(16) __half g_rx[M_ROWS * DIM];

static __device__ __forceinline__ unsigned smem_u32(const void* p) {
    return (unsigned)__cvta_generic_to_shared(p);
}

#define LDM4(d0, d1, d2, d3, a)                                              \
    asm volatile("ldmatrix.sync.aligned.m8n8.x4.shared.b16 {%0,%1,%2,%3}, [%4];" \
                 : "=r"(d0), "=r"(d1), "=r"(d2), "=r"(d3) : "r"(a))

#define MMA16816(c0, c1, c2, c3, a0, a1, a2, a3, b0, b1)                     \
    asm volatile("mma.sync.aligned.m16n8k16.row.col.f32.f16.f16.f32 "        \
                 "{%0,%1,%2,%3}, {%4,%5,%6,%7}, {%8,%9}, {%0,%1,%2,%3};"     \
                 : "+f"(c0), "+f"(c1), "+f"(c2), "+f"(c3)                    \
                 : "r"(a0), "r"(a1), "r"(a2), "r"(a3), "r"(b0), "r"(b1))

// ---------------------------------------------------------------------------
// k1: segment-sum via global f32 atomics. g_psum/g_pcount are zero on entry
// (zero-initialized device globals; finalize_kernel re-zeroes them each call).
// ---------------------------------------------------------------------------
__global__ void accum_kernel(const float* __restrict__ support,
                             const int* __restrict__ labels, int S) {
    int idx = blockIdx.x * blockDim.x + threadIdx.x;
    if (idx >= S * 32) return;
    int r  = idx >> 5;
    int c4 = idx & 31;
    int lbl = labels[r];
    float4 v = ((const float4*)support)[idx];
    float* dst = &g_psum[lbl * DIM + c4 * 4];
    atomicAdd(dst + 0, v.x);
    atomicAdd(dst + 1, v.y);
    atomicAdd(dst + 2, v.z);
    atomicAdd(dst + 3, v.w);
    if (c4 == 0) atomicAdd(&g_pcount[lbl], 1.0f);
}

// ---------------------------------------------------------------------------
// k2: prototype = psum / max(count,1); split into fp16 hi/lo; pnorm = ||p||^2.
// Also re-zeroes g_psum / g_pcount so the next call sees a clean slate.
// ---------------------------------------------------------------------------
__global__ void finalize_kernel() {
    int c = blockIdx.x;
    int d = threadIdx.x;
    float cnt = fmaxf(g_pcount[c], 1.0f);
    float v = g_psum[c * DIM + d] / cnt;
    __half h = __float2half_rn(v);
    g_hp[c * DIM + d] = h;
    g_rp[c * DIM + d] = __float2half_rn(v - __half2float(h));

    float s = v * v;
    #pragma unroll
    for (int o = 16; o > 0; o >>= 1) s += __shfl_xor_sync(0xffffffffu, s, o);
    __shared__ float ws[4];
    if ((d & 31) == 0) ws[d >> 5] = s;
    __syncthreads();
    if (d == 0) {
        g_pnorm[c] = ws[0] + ws[1] + ws[2] + ws[3];
        g_pcount[c] = 0.0f;
    }
    g_psum[c * DIM + d] = 0.0f;
}

// ---------------------------------------------------------------------------
// k0: split x into fp16 hi/lo and compute ||x||^2. One warp per row.
// ---------------------------------------------------------------------------
__global__ void convert_x_kernel(const float* __restrict__ x) {
    int warp = (blockIdx.x * blockDim.x + threadIdx.x) >> 5;
    int lane = threadIdx.x & 31;
    if (warp >= M_ROWS) return;
    float4 v = ((const float4*)x)[warp * 32 + lane];

    __half h0 = __float2half_rn(v.x), h1 = __float2half_rn(v.y);
    __half h2 = __float2half_rn(v.z), h3 = __float2half_rn(v.w);
    union { __half2 h2v[2]; uint2 u; } ph, pr;
    ph.h2v[0] = __halves2half2(h0, h1);
    ph.h2v[1] = __halves2half2(h2, h3);
    pr.h2v[0] = __halves2half2(__float2half_rn(v.x - __half2float(h0)),
                               __float2half_rn(v.y - __half2float(h1)));
    pr.h2v[1] = __halves2half2(__float2half_rn(v.z - __half2float(h2)),
                               __float2half_rn(v.w - __half2float(h3)));
    ((uint2*)(g_hx + (size_t)warp * DIM))[lane] = ph.u;
    ((uint2*)(g_rx + (size_t)warp * DIM))[lane] = pr.u;

    float s = v.x * v.x + v.y * v.y + v.z * v.z + v.w * v.w;
    #pragma unroll
    for (int o = 16; o > 0; o >>= 1) s += __shfl_xor_sync(0xffffffffu, s, o);
    if (lane == 0) g_xnorm[warp] = s;
}

// ---------------------------------------------------------------------------
// k3: tensor-core GEMM.  out[m][n] = 2*dot(x_m,p_n) - ||x_m||^2 - ||p_n||^2
// dot via fp16 split: h·hp + h·rp + r·hp, f32 accumulators.
// BM=128, BN=64, 256 threads, warp grid 4(m)x2(n), warp tile 32x32.
// K=128 resident in smem, XOR swizzle chunk^(row&7) on 16B chunks.
// ---------------------------------------------------------------------------
#define BM 128
#define BN 64
#define GEMM_SMEM 98304   // (128+128)*128*2 + (64+64)*128*2 bytes

__global__ void __launch_bounds__(256, 2)
mma_kernel(float* __restrict__ out) {
    extern __shared__ __half sm[];
    __half* hA = sm;                 // [128][128]
    __half* rA = sm + 16384;
    __half* hB = sm + 32768;         // [64][128]
    __half* rB = sm + 40960;

    int tid = threadIdx.x;
    int m0 = blockIdx.x * BM;
    int n0 = blockIdx.y * BN;

    // ---- load tiles: global (16B) -> swizzled smem ----
    {
        const uint4* ghA = (const uint4*)(g_hx + (size_t)m0 * DIM);
        const uint4* grA = (const uint4*)(g_rx + (size_t)m0 * DIM);
        uint4* shA = (uint4*)hA; uint4* srA = (uint4*)rA;
        #pragma unroll
        for (int i = 0; i < 8; i++) {
            int idx = tid + i * 256;
            int row = idx >> 4, c = idx & 15;
            int sw = c ^ (row & 7);
            shA[row * 16 + sw] = ghA[idx];
            srA[row * 16 + sw] = grA[idx];
        }
        const uint4* ghB = (const uint4*)(g_hp + (size_t)n0 * DIM);
        const uint4* grB = (const uint4*)(g_rp + (size_t)n0 * DIM);
        uint4* shB = (uint4*)hB; uint4* srB = (uint4*)rB;
        #pragma unroll
        for (int i = 0; i < 4; i++) {
            int idx = tid + i * 256;
            int row = idx >> 4, c = idx & 15;
            int sw = c ^ (row & 7);
            shB[row * 16 + sw] = ghB[idx];
            srB[row * 16 + sw] = grB[idx];
        }
    }
    __syncthreads();

    int lane = tid & 31, warp = tid >> 5;
    int wm = warp & 3;        // 0..3  (m direction)
    int wn = warp >> 2;       // 0..1  (n direction)
    int grp = lane >> 3, lr = lane & 7;

    // ldmatrix lane geometry.
    // A: mats {rows0-7 k0}, {rows8-15 k0}, {rows0-7 k8}, {rows8-15 k8}
    int rowA[2], keyA[2];
    #pragma unroll
    for (int ms = 0; ms < 2; ms++) {
        rowA[ms] = wm * 32 + ms * 16 + lr + ((grp & 1) << 3);
        keyA[ms] = rowA[ms] & 7;
    }
    int cAadd = grp >> 1;
    // B: mats {n0-7 k0}, {n0-7 k8}, {n8-15 k0}, {n8-15 k8}
    int rowB[2], keyB[2];
    #pragma unroll
    for (int np = 0; np < 2; np++) {
        rowB[np] = wn * 32 + np * 16 + lr + ((grp >> 1) << 3);
        keyB[np] = rowB[np] & 7;
    }
    int cBadd = grp & 1;

    unsigned baseHA = smem_u32(hA), baseRA = smem_u32(rA);
    unsigned baseHB = smem_u32(hB), baseRB = smem_u32(rB);
    unsigned offA[2], offB[2];
    #pragma unroll
    for (int i = 0; i < 2; i++) { offA[i] = rowA[i] * 256; offB[i] = rowB[i] * 256; }

    float acc[2][4][4];
    #pragma unroll
    for (int i = 0; i < 2; i++)
        #pragma unroll
        for (int j = 0; j < 4; j++)
            #pragma unroll
            for (int k = 0; k < 4; k++) acc[i][j][k] = 0.0f;

    #pragma unroll
    for (int ks = 0; ks < 8; ks++) {
        int kc = ks * 2;
        unsigned ah[2][4], ar[2][4], bh[2][4], br[2][4];
        #pragma unroll
        for (int ms = 0; ms < 2; ms++) {
            unsigned sw = ((unsigned)((kc + cAadd) ^ keyA[ms])) << 4;
            LDM4(ah[ms][0], ah[ms][1], ah[ms][2], ah[ms][3], baseHA + offA[ms] + sw);
            LDM4(ar[ms][0], ar[ms][1], ar[ms][2], ar[ms][3], baseRA + offA[ms] + sw);
        }
        #pragma unroll
        for (int np = 0; np < 2; np++) {
            unsigned sw = ((unsigned)((kc + cBadd) ^ keyB[np])) << 4;
            LDM4(bh[np][0], bh[np][1], bh[np][2], bh[np][3], baseHB + offB[np] + sw);
            LDM4(br[np][0], br[np][1], br[np][2], br[np][3], baseRB + offB[np] + sw);
        }
        #pragma unroll
        for (int ms = 0; ms < 2; ms++) {
            #pragma unroll
            for (int ns = 0; ns < 4; ns++) {
                int np = ns >> 1, o = (ns & 1) * 2;
                float* c = acc[ms][ns];
                MMA16816(c[0], c[1], c[2], c[3],
                         ah[ms][0], ah[ms][1], ah[ms][2], ah[ms][3],
                         bh[np][o], bh[np][o + 1]);
                MMA16816(c[0], c[1], c[2], c[3],
                         ah[ms][0], ah[ms][1], ah[ms][2], ah[ms][3],
                         br[np][o], br[np][o + 1]);
                MMA16816(c[0], c[1], c[2], c[3],
                         ar[ms][0], ar[ms][1], ar[ms][2], ar[ms][3],
                         bh[np][o], bh[np][o + 1]);
            }
        }
    }

    // ---- epilogue: out = 2*dot - xnorm - pnorm ----
    int qrow = lane >> 2;
    int qcol = (lane & 3) * 2;
    #pragma unroll
    for (int ms = 0; ms < 2; ms++) {
        int mrow = m0 + wm * 32 + ms * 16 + qrow;
        float xn0 = __ldg(&g_xnorm[mrow]);
        float xn1 = __ldg(&g_xnorm[mrow + 8]);
        #pragma unroll
        for (int ns = 0; ns < 4; ns++) {
            int n = n0 + wn * 32 + ns * 8 + qcol;
            float pn0 = __ldg(&g_pnorm[n]);
            float pn1 = __ldg(&g_pnorm[n + 1]);
            float* c = acc[ms][ns];
            float2 o0 = make_float2(2.0f * c[0] - xn0 - pn0,
                                    2.0f * c[1] - xn0 - pn1);
            float2 o1 = make_float2(2.0f * c[2] - xn1 - pn0,
                                    2.0f * c[3] - xn1 - pn1);
            *(float2*)&out[(size_t)mrow * N_CLASSES + n] = o0;
            *(float2*)&out[(size_t)(mrow + 8) * N_CLASSES + n] = o1;
        }
    }
}

// ---------------------------------------------------------------------------
extern "C" void kernel_launch(void* const* d_in, const int* in_sizes, int n_in,
                              void* d_out, int out_size) {
    const float* x       = (const float*)d_in[0];
    const float* support = (const float*)d_in[1];
    const int*   labels  = (const int*)d_in[2];
    float* out = (float*)d_out;

    int S = in_sizes[2];  // 4096

    convert_x_kernel<<<M_ROWS / 8, 256>>>(x);
    accum_kernel<<<(S * 32 + 255) / 256, 256>>>(support, labels, S);
    finalize_kernel<<<N_CLASSES, DIM>>>();

    cudaFuncSetAttribute(mma_kernel,
                         cudaFuncAttributeMaxDynamicSharedMemorySize, GEMM_SMEM);
    mma_kernel<<<dim3(M_ROWS / BM, N_CLASSES / BN), 256, GEMM_SMEM>>>(out);
}

// round 3
// speedup vs baseline: 1.8501x; 1.1385x over previous
#include <cuda_runtime.h>
#include <cuda_fp16.h>

#define M_ROWS 8192
#define N_CLASSES 256
#define DIM 128

// ---------------- scratch (__device__ globals; allocation-free rule) -------
__device__ float g_psum[N_CLASSES * DIM];
__device__ float g_pcount[N_CLASSES];
__device__ float g_pnorm[N_CLASSES];
__device__ __align__(16) __half g_hp[N_CLASSES * DIM];
__device__ __align__(16) __half g_rp[N_CLASSES * DIM];

static __device__ __forceinline__ unsigned smem_u32(const void* p) {
    return (unsigned)__cvta_generic_to_shared(p);
}

#define LDM4(d0, d1, d2, d3, a)                                              \
    asm volatile("ldmatrix.sync.aligned.m8n8.x4.shared.b16 {%0,%1,%2,%3}, [%4];" \
                 : "=r"(d0), "=r"(d1), "=r"(d2), "=r"(d3) : "r"(a))

#define MMA16816(c0, c1, c2, c3, a0, a1, a2, a3, b0, b1)                     \
    asm volatile("mma.sync.aligned.m16n8k16.row.col.f32.f16.f16.f32 "        \
                 "{%0,%1,%2,%3}, {%4,%5,%6,%7}, {%8,%9}, {%0,%1,%2,%3};"     \
                 : "+f"(c0), "+f"(c1), "+f"(c2), "+f"(c3)                    \
                 : "r"(a0), "r"(a1), "r"(a2), "r"(a3), "r"(b0), "r"(b1))

// ---------------------------------------------------------------------------
// k1: segment-sum via global f32 atomics. g_psum/g_pcount are zero on entry
// (zero-initialized device globals; finalize_kernel re-zeroes them each call).
// ---------------------------------------------------------------------------
__global__ void accum_kernel(const float* __restrict__ support,
                             const int* __restrict__ labels, int S) {
    int idx = blockIdx.x * blockDim.x + threadIdx.x;
    if (idx >= S * 32) return;
    int r  = idx >> 5;
    int c4 = idx & 31;
    int lbl = labels[r];
    float4 v = ((const float4*)support)[idx];
    float* dst = &g_psum[lbl * DIM + c4 * 4];
    atomicAdd(dst + 0, v.x);
    atomicAdd(dst + 1, v.y);
    atomicAdd(dst + 2, v.z);
    atomicAdd(dst + 3, v.w);
    if (c4 == 0) atomicAdd(&g_pcount[lbl], 1.0f);
}

// ---------------------------------------------------------------------------
// k2: prototype = psum / max(count,1); split to fp16 hi/lo; pnorm = ||p||^2.
// Re-zeroes g_psum / g_pcount for the next graph replay.
// ---------------------------------------------------------------------------
__global__ void finalize_kernel() {
    int c = blockIdx.x;
    int d = threadIdx.x;
    float cnt = fmaxf(g_pcount[c], 1.0f);
    float v = g_psum[c * DIM + d] / cnt;
    __half h = __float2half_rn(v);
    g_hp[c * DIM + d] = h;
    g_rp[c * DIM + d] = __float2half_rn(v - __half2float(h));

    float s = v * v;
    #pragma unroll
    for (int o = 16; o > 0; o >>= 1) s += __shfl_xor_sync(0xffffffffu, s, o);
    __shared__ float ws[4];
    if ((d & 31) == 0) ws[d >> 5] = s;
    __syncthreads();
    if (d == 0) {
        g_pnorm[c] = ws[0] + ws[1] + ws[2] + ws[3];
        g_pcount[c] = 0.0f;
    }
    g_psum[c * DIM + d] = 0.0f;
}

// ---------------------------------------------------------------------------
// k3: fused convert + tensor-core GEMM.
// out[m][n] = 2*dot(x_m,p_n) - ||x_m||^2 - ||p_n||^2
// dot via fp16 split: h·hp + h·rp + r·hp, f32 accumulators.
// BM=128, BN=128, 256 threads, warp grid 4(m)x2(n), warp tile 32x64.
// x loaded as f32, converted in-register to h/r smem tiles; ||x||^2 exact f32.
// K=128 resident, XOR swizzle chunk^(row&7) on 16B chunks.
// ---------------------------------------------------------------------------
#define BM 128
#define BN 128
// hA,rA,hB,rB: 4 * 128*128*2 bytes + 128*4 xnorm
#define GEMM_SMEM (4 * BM * DIM * 2 + BM * 4)

__global__ void __launch_bounds__(256, 1)
mma_kernel(const float* __restrict__ x, float* __restrict__ out) {
    extern __shared__ __half sm[];
    __half* hA = sm;                    // [128][128]
    __half* rA = sm + 16384;
    __half* hB = sm + 32768;            // [128][128]
    __half* rB = sm + 49152;
    float*  xnorm_s = (float*)(sm + 65536);   // [128]

    int tid = threadIdx.x;
    int lane = tid & 31;
    int m0 = blockIdx.x * BM;
    int n0 = blockIdx.y * BN;

    // ---- load x tile (f32), convert to h/r, swizzled smem; ||x||^2 ----
    {
        const float4* gx = (const float4*)(x + (size_t)m0 * DIM);
        uint4* shA = (uint4*)hA;
        uint4* srA = (uint4*)rA;
        #pragma unroll
        for (int i = 0; i < 8; i++) {
            int idx = tid + i * 256;        // 0..2047 (16B chunk id)
            int row = idx >> 4, c = idx & 15;
            float4 v0 = gx[row * 32 + c * 2];
            float4 v1 = gx[row * 32 + c * 2 + 1];

            union { __half2 q[4]; uint4 u; } H, R;
            H.q[0] = __floats2half2_rn(v0.x, v0.y);
            H.q[1] = __floats2half2_rn(v0.z, v0.w);
            H.q[2] = __floats2half2_rn(v1.x, v1.y);
            H.q[3] = __floats2half2_rn(v1.z, v1.w);
            float2 f0 = __half22float2(H.q[0]);
            float2 f1 = __half22float2(H.q[1]);
            float2 f2 = __half22float2(H.q[2]);
            float2 f3 = __half22float2(H.q[3]);
            R.q[0] = __floats2half2_rn(v0.x - f0.x, v0.y - f0.y);
            R.q[1] = __floats2half2_rn(v0.z - f1.x, v0.w - f1.y);
            R.q[2] = __floats2half2_rn(v1.x - f2.x, v1.y - f2.y);
            R.q[3] = __floats2half2_rn(v1.z - f3.x, v1.w - f3.y);

            int sw = c ^ (row & 7);
            shA[row * 16 + sw] = H.u;
            srA[row * 16 + sw] = R.u;

            float s = v0.x * v0.x + v0.y * v0.y + v0.z * v0.z + v0.w * v0.w
                    + v1.x * v1.x + v1.y * v1.y + v1.z * v1.z + v1.w * v1.w;
            #pragma unroll
            for (int o = 1; o < 16; o <<= 1)
                s += __shfl_xor_sync(0xffffffffu, s, o);
            if ((lane & 15) == 0) xnorm_s[row] = s;
        }
    }
    // ---- load prototype tiles (already fp16 h/r) ----
    {
        const uint4* ghB = (const uint4*)(g_hp + (size_t)n0 * DIM);
        const uint4* grB = (const uint4*)(g_rp + (size_t)n0 * DIM);
        uint4* shB = (uint4*)hB;
        uint4* srB = (uint4*)rB;
        #pragma unroll
        for (int i = 0; i < 8; i++) {
            int idx = tid + i * 256;
            int row = idx >> 4, c = idx & 15;
            int sw = c ^ (row & 7);
            shB[row * 16 + sw] = ghB[idx];
            srB[row * 16 + sw] = grB[idx];
        }
    }
    __syncthreads();

    int warp = tid >> 5;
    int wm = warp & 3;        // 0..3  (m, 32 rows each)
    int wn = warp >> 2;       // 0..1  (n, 64 cols each)
    int grp = lane >> 3, lr = lane & 7;

    // ldmatrix lane geometry (same scheme as validated round-2 kernel).
    int rowA[2], keyA[2];
    #pragma unroll
    for (int ms = 0; ms < 2; ms++) {
        rowA[ms] = wm * 32 + ms * 16 + lr + ((grp & 1) << 3);
        keyA[ms] = rowA[ms] & 7;
    }
    int cAadd = grp >> 1;
    int rowB[4], keyB[4];
    #pragma unroll
    for (int np = 0; np < 4; np++) {
        rowB[np] = wn * 64 + np * 16 + lr + ((grp >> 1) << 3);
        keyB[np] = rowB[np] & 7;
    }
    int cBadd = grp & 1;

    unsigned baseHA = smem_u32(hA), baseRA = smem_u32(rA);
    unsigned baseHB = smem_u32(hB), baseRB = smem_u32(rB);
    unsigned offA[2], offB[4];
    #pragma unroll
    for (int i = 0; i < 2; i++) offA[i] = rowA[i] * 256;
    #pragma unroll
    for (int i = 0; i < 4; i++) offB[i] = rowB[i] * 256;

    float acc[2][8][4];
    #pragma unroll
    for (int i = 0; i < 2; i++)
        #pragma unroll
        for (int j = 0; j < 8; j++)
            #pragma unroll
            for (int k = 0; k < 4; k++) acc[i][j][k] = 0.0f;

    #pragma unroll
    for (int ks = 0; ks < 8; ks++) {
        int kc = ks * 2;
        unsigned ah[2][4], ar[2][4], bh[4][4], br[4][4];
        #pragma unroll
        for (int ms = 0; ms < 2; ms++) {
            unsigned sw = ((unsigned)((kc + cAadd) ^ keyA[ms])) << 4;
            LDM4(ah[ms][0], ah[ms][1], ah[ms][2], ah[ms][3], baseHA + offA[ms] + sw);
            LDM4(ar[ms][0], ar[ms][1], ar[ms][2], ar[ms][3], baseRA + offA[ms] + sw);
        }
        #pragma unroll
        for (int np = 0; np < 4; np++) {
            unsigned sw = ((unsigned)((kc + cBadd) ^ keyB[np])) << 4;
            LDM4(bh[np][0], bh[np][1], bh[np][2], bh[np][3], baseHB + offB[np] + sw);
            LDM4(br[np][0], br[np][1], br[np][2], br[np][3], baseRB + offB[np] + sw);
        }
        #pragma unroll
        for (int ms = 0; ms < 2; ms++) {
            #pragma unroll
            for (int ns = 0; ns < 8; ns++) {
                int np = ns >> 1, o = (ns & 1) * 2;
                float* c = acc[ms][ns];
                MMA16816(c[0], c[1], c[2], c[3],
                         ah[ms][0], ah[ms][1], ah[ms][2], ah[ms][3],
                         bh[np][o], bh[np][o + 1]);
                MMA16816(c[0], c[1], c[2], c[3],
                         ah[ms][0], ah[ms][1], ah[ms][2], ah[ms][3],
                         br[np][o], br[np][o + 1]);
                MMA16816(c[0], c[1], c[2], c[3],
                         ar[ms][0], ar[ms][1], ar[ms][2], ar[ms][3],
                         bh[np][o], bh[np][o + 1]);
            }
        }
    }

    // ---- epilogue: out = 2*dot - xnorm - pnorm ----
    int qrow = lane >> 2;
    int qcol = (lane & 3) * 2;
    #pragma unroll
    for (int ms = 0; ms < 2; ms++) {
        int lrow = wm * 32 + ms * 16 + qrow;
        int mrow = m0 + lrow;
        float xn0 = xnorm_s[lrow];
        float xn1 = xnorm_s[lrow + 8];
        #pragma unroll
        for (int ns = 0; ns < 8; ns++) {
            int n = n0 + wn * 64 + ns * 8 + qcol;
            float pn0 = __ldg(&g_pnorm[n]);
            float pn1 = __ldg(&g_pnorm[n + 1]);
            float* c = acc[ms][ns];
            float2 o0 = make_float2(2.0f * c[0] - xn0 - pn0,
                                    2.0f * c[1] - xn0 - pn1);
            float2 o1 = make_float2(2.0f * c[2] - xn1 - pn0,
                                    2.0f * c[3] - xn1 - pn1);
            *(float2*)&out[(size_t)mrow * N_CLASSES + n] = o0;
            *(float2*)&out[(size_t)(mrow + 8) * N_CLASSES + n] = o1;
        }
    }
}

// ---------------------------------------------------------------------------
extern "C" void kernel_launch(void* const* d_in, const int* in_sizes, int n_in,
                              void* d_out, int out_size) {
    const float* x       = (const float*)d_in[0];
    const float* support = (const float*)d_in[1];
    const int*   labels  = (const int*)d_in[2];
    float* out = (float*)d_out;

    int S = in_sizes[2];  // 4096

    accum_kernel<<<(S * 32 + 255) / 256, 256>>>(support, labels, S);
    finalize_kernel<<<N_CLASSES, DIM>>>();

    cudaFuncSetAttribute(mma_kernel,
                         cudaFuncAttributeMaxDynamicSharedMemorySize, GEMM_SMEM);
    mma_kernel<<<dim3(M_ROWS / BM, N_CLASSES / BN), 256, GEMM_SMEM>>>(x, out);
}